// round 2
// baseline (speedup 1.0000x reference)
#include <cuda_runtime.h>
#include <math.h>

#define NHEADS 16
#define INDIM  1024
#define DHEAD  64
#define BATCH  2
#define SEQ    2048
#define NTOK   (BATCH*SEQ)

// Padded stride for transposed SMEM tiles: multiple of 4 floats (float4-aligned)
// but not a multiple of 32 (breaks bank periodicity for transposed access).
#define PAD 68

// Scratch for projected q/k/v, layout [B*H][S][DHEAD]. 16.8 MB each.
__device__ float g_q[(size_t)BATCH*NHEADS*SEQ*DHEAD];
__device__ float g_k[(size_t)BATCH*NHEADS*SEQ*DHEAD];
__device__ float g_v[(size_t)BATCH*NHEADS*SEQ*DHEAD];

// ---------------------------------------------------------------------------
// Projection: C[m][n] = sum_k X[m][k] * W[h][k][n] + b[h][n]
// Grid: (NTOK/64, NHEADS, 3)   proj 0=q, 1=k, 2=v
// BM=64, BN=64, BK=32, 256 threads, 4x4 register microtile per thread.
// ---------------------------------------------------------------------------
__global__ __launch_bounds__(256)
void proj_kernel(const float* __restrict__ x,
                 const float* __restrict__ Wq, const float* __restrict__ bq,
                 const float* __restrict__ Wk, const float* __restrict__ bk,
                 const float* __restrict__ Wv, const float* __restrict__ bv)
{
    __shared__ float As[32][PAD];  // [k][m]  (transposed, padded)
    __shared__ float Bs[32][64];   // [k][n]

    const int mbase = blockIdx.x * 64;
    const int h     = blockIdx.y;
    const int proj  = blockIdx.z;

    const float* W    = (proj == 0) ? Wq : (proj == 1) ? Wk : Wv;
    const float* bias = (proj == 0) ? bq : (proj == 1) ? bk : bv;
    float*       outp = (proj == 0) ? g_q : (proj == 1) ? g_k : g_v;
    W    += (size_t)h * INDIM * DHEAD;
    bias += h * DHEAD;

    const int tid = threadIdx.x;
    const int tx  = tid & 15;     // column group (n)
    const int ty  = tid >> 4;     // row group (m)

    float acc[4][4];
#pragma unroll
    for (int i = 0; i < 4; i++)
#pragma unroll
        for (int j = 0; j < 4; j++) acc[i][j] = 0.f;

    for (int k0 = 0; k0 < INDIM; k0 += 32) {
        // Load A tile 64x32 (transposed into As) and B tile 32x64.
#pragma unroll
        for (int it = 0; it < 2; it++) {
            int idx = tid + it * 256;            // 512 float4 slots each
            int r   = idx >> 3;                  // 64 rows x 8 float4
            int kk  = (idx & 7) << 2;
            float4 a4 = *(const float4*)(x + (size_t)(mbase + r) * INDIM + k0 + kk);
            As[kk + 0][r] = a4.x; As[kk + 1][r] = a4.y;
            As[kk + 2][r] = a4.z; As[kk + 3][r] = a4.w;

            int kb = idx >> 4;                   // 32 rows x 16 float4
            int n  = (idx & 15) << 2;
            *(float4*)(&Bs[kb][n]) = *(const float4*)(W + (size_t)(k0 + kb) * DHEAD + n);
        }
        __syncthreads();

#pragma unroll
        for (int kk = 0; kk < 32; kk++) {
            float4 a4 = *(const float4*)(&As[kk][ty << 2]);
            float4 b4 = *(const float4*)(&Bs[kk][tx << 2]);
            float a[4] = {a4.x, a4.y, a4.z, a4.w};
            float b[4] = {b4.x, b4.y, b4.z, b4.w};
#pragma unroll
            for (int i = 0; i < 4; i++)
#pragma unroll
                for (int j = 0; j < 4; j++)
                    acc[i][j] += a[i] * b[j];
        }
        __syncthreads();
    }

    float4 bb = *(const float4*)(bias + (tx << 2));
    float bj[4] = {bb.x, bb.y, bb.z, bb.w};
#pragma unroll
    for (int i = 0; i < 4; i++) {
        int m = mbase + (ty << 2) + i;
        int b = m / SEQ, s = m % SEQ;
        float* o = outp + ((size_t)(b * NHEADS + h) * SEQ + s) * DHEAD + (tx << 2);
        *(float4*)o = make_float4(acc[i][0] + bj[0], acc[i][1] + bj[1],
                                  acc[i][2] + bj[2], acc[i][3] + bj[3]);
    }
}

// ---------------------------------------------------------------------------
// Flash attention (fp32): per (64-query tile, b*h).
// Online softmax; reference applies softmax FIRST then divides by sqrt(64)=8,
// so epilogue scale is 1/(l * 8). No pre-softmax scale on the scores.
// Grid: (SEQ/64, BATCH*NHEADS), 256 threads (16x16).
// Dynamic SMEM: Qs[64][PAD] + Ks[64][PAD] (reused as Ps) + Vs[64][64] floats.
// ---------------------------------------------------------------------------
#define ATTN_SMEM_BYTES ((2*64*PAD + 64*64) * 4)

__global__ __launch_bounds__(256)
void attn_kernel(float* __restrict__ out)
{
    extern __shared__ float sm[];
    float* Qs = sm;                  // [d][r] stride PAD
    float* Ks = sm + 64 * PAD;       // [d][c] stride PAD; reused as Ps[c][r]
    float* Vs = sm + 2 * 64 * PAD;   // [c][v] stride 64

    const int qbase = blockIdx.x * 64;
    const int bh    = blockIdx.y;
    const float* Q = g_q + (size_t)bh * SEQ * DHEAD;
    const float* K = g_k + (size_t)bh * SEQ * DHEAD;
    const float* V = g_v + (size_t)bh * SEQ * DHEAD;

    const int tid = threadIdx.x;
    const int tx  = tid & 15;       // key-col / v-col group
    const int ty  = tid >> 4;       // query-row group

    // Load Q tile transposed: Qs[d][r]
#pragma unroll
    for (int it = 0; it < 4; it++) {
        int idx = tid + it * 256;   // 1024 float4 slots
        int r   = idx >> 4;
        int d   = (idx & 15) << 2;
        float4 a4 = *(const float4*)(Q + (size_t)(qbase + r) * DHEAD + d);
        Qs[(d + 0) * PAD + r] = a4.x; Qs[(d + 1) * PAD + r] = a4.y;
        Qs[(d + 2) * PAD + r] = a4.z; Qs[(d + 3) * PAD + r] = a4.w;
    }

    float m[4], l[4], acc[4][4];
#pragma unroll
    for (int i = 0; i < 4; i++) {
        m[i] = -1e30f; l[i] = 0.f;
#pragma unroll
        for (int j = 0; j < 4; j++) acc[i][j] = 0.f;
    }

    for (int kb = 0; kb < SEQ; kb += 64) {
        __syncthreads();   // previous-iter PV readers done (also covers Q store, iter 0)

        // Load K chunk transposed + V chunk natural
#pragma unroll
        for (int it = 0; it < 4; it++) {
            int idx = tid + it * 256;
            int r   = idx >> 4;
            int d   = (idx & 15) << 2;
            float4 k4 = *(const float4*)(K + (size_t)(kb + r) * DHEAD + d);
            Ks[(d + 0) * PAD + r] = k4.x; Ks[(d + 1) * PAD + r] = k4.y;
            Ks[(d + 2) * PAD + r] = k4.z; Ks[(d + 3) * PAD + r] = k4.w;
            *(float4*)(&Vs[r * 64 + d]) = *(const float4*)(V + (size_t)(kb + r) * DHEAD + d);
        }
        __syncthreads();

        // Scores: s[r][c] = sum_d Q[r][d] * K[c][d]
        float s[4][4];
#pragma unroll
        for (int i = 0; i < 4; i++)
#pragma unroll
            for (int j = 0; j < 4; j++) s[i][j] = 0.f;

#pragma unroll 8
        for (int d = 0; d < 64; d++) {
            float4 q4 = *(const float4*)(&Qs[d * PAD + (ty << 2)]);
            float4 k4 = *(const float4*)(&Ks[d * PAD + (tx << 2)]);
            float qa[4] = {q4.x, q4.y, q4.z, q4.w};
            float ka[4] = {k4.x, k4.y, k4.z, k4.w};
#pragma unroll
            for (int i = 0; i < 4; i++)
#pragma unroll
                for (int j = 0; j < 4; j++)
                    s[i][j] += qa[i] * ka[j];
        }

        // Online softmax. Threads sharing a query row (same ty, tx=0..15) occupy
        // one 16-lane half of a warp -> shfl_xor with offsets <16 stays in-row.
#pragma unroll
        for (int i = 0; i < 4; i++) {
            float mx = fmaxf(fmaxf(s[i][0], s[i][1]), fmaxf(s[i][2], s[i][3]));
#pragma unroll
            for (int off = 1; off < 16; off <<= 1)
                mx = fmaxf(mx, __shfl_xor_sync(0xffffffffu, mx, off));
            float mnew  = fmaxf(m[i], mx);
            float alpha = __expf(m[i] - mnew);
            float ps = 0.f;
#pragma unroll
            for (int j = 0; j < 4; j++) { s[i][j] = __expf(s[i][j] - mnew); ps += s[i][j]; }
#pragma unroll
            for (int off = 1; off < 16; off <<= 1)
                ps += __shfl_xor_sync(0xffffffffu, ps, off);
            l[i] = l[i] * alpha + ps;
            m[i] = mnew;
#pragma unroll
            for (int j = 0; j < 4; j++) acc[i][j] *= alpha;
        }

        __syncthreads();   // everyone done reading Ks before overwriting as Ps
        // Store P transposed: Ps[c][r] (aliases Ks)
#pragma unroll
        for (int i = 0; i < 4; i++)
#pragma unroll
            for (int j = 0; j < 4; j++)
                Ks[((tx << 2) + j) * PAD + (ty << 2) + i] = s[i][j];
        __syncthreads();

        // PV: acc[r][v] += P[r][c] * V[c][v]
#pragma unroll 8
        for (int c = 0; c < 64; c++) {
            float4 p4 = *(const float4*)(&Ks[c * PAD + (ty << 2)]);
            float4 v4 = *(const float4*)(&Vs[c * 64 + (tx << 2)]);
            float pa[4] = {p4.x, p4.y, p4.z, p4.w};
            float va[4] = {v4.x, v4.y, v4.z, v4.w};
#pragma unroll
            for (int i = 0; i < 4; i++)
#pragma unroll
                for (int j = 0; j < 4; j++)
                    acc[i][j] += pa[i] * va[j];
        }
    }

    // Epilogue: out[b][s][h*64 + v] = acc / (l * sqrt(64))
    const int b = bh >> 4, h = bh & 15;
#pragma unroll
    for (int i = 0; i < 4; i++) {
        float inv  = 1.0f / (l[i] * 8.0f);
        int   srow = qbase + (ty << 2) + i;
        float* o = out + ((size_t)(b * SEQ + srow)) * (NHEADS * DHEAD) + h * DHEAD + (tx << 2);
        *(float4*)o = make_float4(acc[i][0] * inv, acc[i][1] * inv,
                                  acc[i][2] * inv, acc[i][3] * inv);
    }
}

// ---------------------------------------------------------------------------
extern "C" void kernel_launch(void* const* d_in, const int* in_sizes, int n_in,
                              void* d_out, int out_size)
{
    const float* x  = (const float*)d_in[0];
    const float* Wq = (const float*)d_in[1];
    const float* bq = (const float*)d_in[2];
    const float* Wk = (const float*)d_in[3];
    const float* bk = (const float*)d_in[4];
    const float* Wv = (const float*)d_in[5];
    const float* bv = (const float*)d_in[6];
    float* out = (float*)d_out;

    static int configured = 0;
    if (!configured) {
        cudaFuncSetAttribute(attn_kernel,
                             cudaFuncAttributeMaxDynamicSharedMemorySize,
                             ATTN_SMEM_BYTES);
        configured = 1;
    }

    proj_kernel<<<dim3(NTOK / 64, NHEADS, 3), 256>>>(x, Wq, bq, Wk, bk, Wv, bv);
    attn_kernel<<<dim3(SEQ / 64, BATCH * NHEADS), 256, ATTN_SMEM_BYTES>>>(out);
}